// round 6
// baseline (speedup 1.0000x reference)
#include <cuda_runtime.h>

// SparseTransE on GB300 — R4: 2 triples per warp for 2x memory-level parallelism.
//
// Inputs (metadata order):
//   d_in[0] all_emb  : float32 [501000, 256]
//   d_in[1..3] pos_h/r/t : int32 [65536]
//   d_in[4..6] neg_h/r/t : int32 [65536]
// Output: float32 [131072] = concat(pos_scores, neg_scores)
//
// score(h,r,t) = -|| e[h]/max(||e[h]||,eps) + e[r+n_ent] - e[t]/max(||e[t]||,eps) ||^2
//
// Never materialize the normalized table; normalize gathered rows on the fly.
// Each warp handles scores {2w, 2w+1} (always in the same pos/neg half).
// Front-batch the 8 DRAM-latency entity loads, then the 4 L2-hit relation
// loads, then compute. Fused butterfly reductions.

#define N_BATCH 65536
#define EMB     256
#define N_ENT   500000
#define EPS2    1e-24f   // (1e-12)^2 — guard matches max(norm, 1e-12)

__global__ __launch_bounds__(256)
void sparse_transe_kernel(
    const float* __restrict__ emb,
    const int*   __restrict__ pos_h,
    const int*   __restrict__ pos_r,
    const int*   __restrict__ pos_t,
    const int*   __restrict__ neg_h,
    const int*   __restrict__ neg_r,
    const int*   __restrict__ neg_t,
    float*       __restrict__ out)
{
    const int warp = (blockIdx.x * blockDim.x + threadIdx.x) >> 5;  // 0..65535
    const int lane = threadIdx.x & 31;

    const int s0 = 2 * warp;          // first score index
    // Both s0 and s0+1 are in the same half since N_BATCH is even.
    const int* __restrict__ H;
    const int* __restrict__ R;
    const int* __restrict__ T;
    int i0;
    if (s0 < N_BATCH) { H = pos_h; R = pos_r; T = pos_t; i0 = s0; }
    else              { H = neg_h; R = neg_r; T = neg_t; i0 = s0 - N_BATCH; }
    const int i1 = i0 + 1;

    // Row bases (64-bit; table is 501000*256 floats ≈ 513 MB).
    const long ha = (long)__ldg(H + i0) * EMB;
    const long ta = (long)__ldg(T + i0) * EMB;
    const long hb = (long)__ldg(H + i1) * EMB;
    const long tb = (long)__ldg(T + i1) * EMB;
    const long ra = ((long)__ldg(R + i0) + N_ENT) * EMB;
    const long rb = ((long)__ldg(R + i1) + N_ENT) * EMB;

    const float4* __restrict__ pha = (const float4*)(emb + ha);
    const float4* __restrict__ pta = (const float4*)(emb + ta);
    const float4* __restrict__ phb = (const float4*)(emb + hb);
    const float4* __restrict__ ptb = (const float4*)(emb + tb);
    const float4* __restrict__ pra = (const float4*)(emb + ra);
    const float4* __restrict__ prb = (const float4*)(emb + rb);

    // ── Front-batch the 8 entity (DRAM-latency) loads ──
    float4 Ah0 = pha[lane];
    float4 Ah1 = pha[lane + 32];
    float4 At0 = pta[lane];
    float4 At1 = pta[lane + 32];
    float4 Bh0 = phb[lane];
    float4 Bh1 = phb[lane + 32];
    float4 Bt0 = ptb[lane];
    float4 Bt1 = ptb[lane + 32];
    // ── Relation loads (L2-resident, shorter latency) ──
    float4 Ar0 = pra[lane];
    float4 Ar1 = pra[lane + 32];
    float4 Br0 = prb[lane];
    float4 Br1 = prb[lane + 32];

    // Partial squared norms.
    float shA = Ah0.x*Ah0.x + Ah0.y*Ah0.y + Ah0.z*Ah0.z + Ah0.w*Ah0.w
              + Ah1.x*Ah1.x + Ah1.y*Ah1.y + Ah1.z*Ah1.z + Ah1.w*Ah1.w;
    float stA = At0.x*At0.x + At0.y*At0.y + At0.z*At0.z + At0.w*At0.w
              + At1.x*At1.x + At1.y*At1.y + At1.z*At1.z + At1.w*At1.w;
    float shB = Bh0.x*Bh0.x + Bh0.y*Bh0.y + Bh0.z*Bh0.z + Bh0.w*Bh0.w
              + Bh1.x*Bh1.x + Bh1.y*Bh1.y + Bh1.z*Bh1.z + Bh1.w*Bh1.w;
    float stB = Bt0.x*Bt0.x + Bt0.y*Bt0.y + Bt0.z*Bt0.z + Bt0.w*Bt0.w
              + Bt1.x*Bt1.x + Bt1.y*Bt1.y + Bt1.z*Bt1.z + Bt1.w*Bt1.w;

    // Fused 4-way butterfly reduction.
    #pragma unroll
    for (int off = 16; off > 0; off >>= 1) {
        shA += __shfl_xor_sync(0xffffffffu, shA, off);
        stA += __shfl_xor_sync(0xffffffffu, stA, off);
        shB += __shfl_xor_sync(0xffffffffu, shB, off);
        stB += __shfl_xor_sync(0xffffffffu, stB, off);
    }

    const float ihA = rsqrtf(fmaxf(shA, EPS2));
    const float itA = rsqrtf(fmaxf(stA, EPS2));
    const float ihB = rsqrtf(fmaxf(shB, EPS2));
    const float itB = rsqrtf(fmaxf(stB, EPS2));

    // v = h/|h| + r - t/|t| ; accumulate v^2 per triple.
    float accA = 0.f, accB = 0.f;
    {
        float d;
        d = fmaf(Ah0.x, ihA, Ar0.x) - At0.x * itA; accA = fmaf(d, d, accA);
        d = fmaf(Ah0.y, ihA, Ar0.y) - At0.y * itA; accA = fmaf(d, d, accA);
        d = fmaf(Ah0.z, ihA, Ar0.z) - At0.z * itA; accA = fmaf(d, d, accA);
        d = fmaf(Ah0.w, ihA, Ar0.w) - At0.w * itA; accA = fmaf(d, d, accA);
        d = fmaf(Ah1.x, ihA, Ar1.x) - At1.x * itA; accA = fmaf(d, d, accA);
        d = fmaf(Ah1.y, ihA, Ar1.y) - At1.y * itA; accA = fmaf(d, d, accA);
        d = fmaf(Ah1.z, ihA, Ar1.z) - At1.z * itA; accA = fmaf(d, d, accA);
        d = fmaf(Ah1.w, ihA, Ar1.w) - At1.w * itA; accA = fmaf(d, d, accA);

        d = fmaf(Bh0.x, ihB, Br0.x) - Bt0.x * itB; accB = fmaf(d, d, accB);
        d = fmaf(Bh0.y, ihB, Br0.y) - Bt0.y * itB; accB = fmaf(d, d, accB);
        d = fmaf(Bh0.z, ihB, Br0.z) - Bt0.z * itB; accB = fmaf(d, d, accB);
        d = fmaf(Bh0.w, ihB, Br0.w) - Bt0.w * itB; accB = fmaf(d, d, accB);
        d = fmaf(Bh1.x, ihB, Br1.x) - Bt1.x * itB; accB = fmaf(d, d, accB);
        d = fmaf(Bh1.y, ihB, Br1.y) - Bt1.y * itB; accB = fmaf(d, d, accB);
        d = fmaf(Bh1.z, ihB, Br1.z) - Bt1.z * itB; accB = fmaf(d, d, accB);
        d = fmaf(Bh1.w, ihB, Br1.w) - Bt1.w * itB; accB = fmaf(d, d, accB);
    }

    // Fused 2-way butterfly reduction.
    #pragma unroll
    for (int off = 16; off > 0; off >>= 1) {
        accA += __shfl_xor_sync(0xffffffffu, accA, off);
        accB += __shfl_xor_sync(0xffffffffu, accB, off);
    }

    if (lane == 0) {
        out[s0]     = -accA;
        out[s0 + 1] = -accB;
    }
}

extern "C" void kernel_launch(void* const* d_in, const int* in_sizes, int n_in,
                              void* d_out, int out_size)
{
    const float* emb   = (const float*)d_in[0];
    const int*   pos_h = (const int*)d_in[1];
    const int*   pos_r = (const int*)d_in[2];
    const int*   pos_t = (const int*)d_in[3];
    const int*   neg_h = (const int*)d_in[4];
    const int*   neg_r = (const int*)d_in[5];
    const int*   neg_t = (const int*)d_in[6];
    float* out = (float*)d_out;

    // 131072 scores, 2 per warp -> 65536 warps, 8 warps/block -> 8192 blocks.
    const int blocks = (2 * N_BATCH) / 2 / 8;
    sparse_transe_kernel<<<blocks, 256>>>(
        emb, pos_h, pos_r, pos_t, neg_h, neg_r, neg_t, out);
}

// round 12
// speedup vs baseline: 1.0571x; 1.0571x over previous
#include <cuda_runtime.h>

// SparseTransE on GB300 — R12 (resubmit of R11; round 11 was an infra failure,
// the kernel never executed).
// R3 shape (1 triple/warp, 6 front-batched float4 loads, 256-thread blocks)
// + algebraic restructure: expand ||h/|h| + r - t/|t|||^2 into 6 dot
// products (h.h, t.t, r.r, h.r, h.t, r.t) that are all independent of the
// normalization, so the warp does ONE fused 6-value butterfly reduction
// instead of two dependent reduction phases around an rsqrt. Cuts ~200
// cycles of serial post-load latency per warp -> faster warp turnover ->
// more loads in flight per SM.
//
// Inputs (metadata order):
//   d_in[0] all_emb  : float32 [501000, 256]
//   d_in[1..3] pos_h/r/t : int32 [65536]
//   d_in[4..6] neg_h/r/t : int32 [65536]
// Output: float32 [131072] = concat(pos_scores, neg_scores)

#define N_BATCH 65536
#define EMB     256
#define N_ENT   500000
#define EPS2    1e-24f   // (1e-12)^2 — guard matches max(norm, 1e-12)

__global__ __launch_bounds__(256)
void sparse_transe_kernel(
    const float* __restrict__ emb,
    const int*   __restrict__ pos_h,
    const int*   __restrict__ pos_r,
    const int*   __restrict__ pos_t,
    const int*   __restrict__ neg_h,
    const int*   __restrict__ neg_r,
    const int*   __restrict__ neg_t,
    float*       __restrict__ out)
{
    const int gwarp = (blockIdx.x * blockDim.x + threadIdx.x) >> 5;  // 0..131071
    const int lane  = threadIdx.x & 31;

    const int* __restrict__ H;
    const int* __restrict__ R;
    const int* __restrict__ T;
    int i;
    if (gwarp < N_BATCH) { H = pos_h; R = pos_r; T = pos_t; i = gwarp; }
    else                 { H = neg_h; R = neg_r; T = neg_t; i = gwarp - N_BATCH; }

    // Warp-uniform index loads.
    const long hrow = (long)__ldg(H + i) * EMB;
    const long trow = (long)__ldg(T + i) * EMB;
    const long rrow = ((long)__ldg(R + i) + N_ENT) * EMB;

    const float4* __restrict__ hp = (const float4*)(emb + hrow);
    const float4* __restrict__ tp = (const float4*)(emb + trow);
    const float4* __restrict__ rp = (const float4*)(emb + rrow);

    // Front-batch all 6 loads (entity rows first — DRAM latency; relation
    // rows are L2-resident).
    float4 h0 = hp[lane];
    float4 h1 = hp[lane + 32];
    float4 t0 = tp[lane];
    float4 t1 = tp[lane + 32];
    float4 r0 = rp[lane];
    float4 r1 = rp[lane + 32];

    // Six partial dot products — all independent of the reductions.
    float sh  = 0.f, st  = 0.f, srr = 0.f;
    float shr = 0.f, sht = 0.f, srt = 0.f;
    {
        sh  = fmaf(h0.x, h0.x, sh);  sh  = fmaf(h0.y, h0.y, sh);
        sh  = fmaf(h0.z, h0.z, sh);  sh  = fmaf(h0.w, h0.w, sh);
        sh  = fmaf(h1.x, h1.x, sh);  sh  = fmaf(h1.y, h1.y, sh);
        sh  = fmaf(h1.z, h1.z, sh);  sh  = fmaf(h1.w, h1.w, sh);

        st  = fmaf(t0.x, t0.x, st);  st  = fmaf(t0.y, t0.y, st);
        st  = fmaf(t0.z, t0.z, st);  st  = fmaf(t0.w, t0.w, st);
        st  = fmaf(t1.x, t1.x, st);  st  = fmaf(t1.y, t1.y, st);
        st  = fmaf(t1.z, t1.z, st);  st  = fmaf(t1.w, t1.w, st);

        srr = fmaf(r0.x, r0.x, srr); srr = fmaf(r0.y, r0.y, srr);
        srr = fmaf(r0.z, r0.z, srr); srr = fmaf(r0.w, r0.w, srr);
        srr = fmaf(r1.x, r1.x, srr); srr = fmaf(r1.y, r1.y, srr);
        srr = fmaf(r1.z, r1.z, srr); srr = fmaf(r1.w, r1.w, srr);

        shr = fmaf(h0.x, r0.x, shr); shr = fmaf(h0.y, r0.y, shr);
        shr = fmaf(h0.z, r0.z, shr); shr = fmaf(h0.w, r0.w, shr);
        shr = fmaf(h1.x, r1.x, shr); shr = fmaf(h1.y, r1.y, shr);
        shr = fmaf(h1.z, r1.z, shr); shr = fmaf(h1.w, r1.w, shr);

        sht = fmaf(h0.x, t0.x, sht); sht = fmaf(h0.y, t0.y, sht);
        sht = fmaf(h0.z, t0.z, sht); sht = fmaf(h0.w, t0.w, sht);
        sht = fmaf(h1.x, t1.x, sht); sht = fmaf(h1.y, t1.y, sht);
        sht = fmaf(h1.z, t1.z, sht); sht = fmaf(h1.w, t1.w, sht);

        srt = fmaf(r0.x, t0.x, srt); srt = fmaf(r0.y, t0.y, srt);
        srt = fmaf(r0.z, t0.z, srt); srt = fmaf(r0.w, t0.w, srt);
        srt = fmaf(r1.x, t1.x, srt); srt = fmaf(r1.y, t1.y, srt);
        srt = fmaf(r1.z, t1.z, srt); srt = fmaf(r1.w, t1.w, srt);
    }

    // ONE fused 6-value butterfly reduction (shuffles pipeline per step).
    #pragma unroll
    for (int off = 16; off > 0; off >>= 1) {
        sh  += __shfl_xor_sync(0xffffffffu, sh,  off);
        st  += __shfl_xor_sync(0xffffffffu, st,  off);
        srr += __shfl_xor_sync(0xffffffffu, srr, off);
        shr += __shfl_xor_sync(0xffffffffu, shr, off);
        sht += __shfl_xor_sync(0xffffffffu, sht, off);
        srt += __shfl_xor_sync(0xffffffffu, srt, off);
    }

    if (lane == 0) {
        const float ih = rsqrtf(fmaxf(sh, EPS2));
        const float it = rsqrtf(fmaxf(st, EPS2));
        // ||h*ih + r - t*it||^2
        //  = sh*ih^2 + srr + st*it^2 + 2*(shr*ih - sht*ih*it - srt*it)
        const float quad  = fmaf(sh, ih * ih, fmaf(st, it * it, srr));
        const float cross = shr * ih - (sht * ih) * it - srt * it;
        out[gwarp] = -fmaf(2.f, cross, quad);
    }
}

extern "C" void kernel_launch(void* const* d_in, const int* in_sizes, int n_in,
                              void* d_out, int out_size)
{
    const float* emb   = (const float*)d_in[0];
    const int*   pos_h = (const int*)d_in[1];
    const int*   pos_r = (const int*)d_in[2];
    const int*   pos_t = (const int*)d_in[3];
    const int*   neg_h = (const int*)d_in[4];
    const int*   neg_r = (const int*)d_in[5];
    const int*   neg_t = (const int*)d_in[6];
    float* out = (float*)d_out;

    // 131072 warps, 8 warps (256 threads) per block -> 16384 blocks.
    const int blocks = (2 * N_BATCH) / 8;
    sparse_transe_kernel<<<blocks, 256>>>(
        emb, pos_h, pos_r, pos_t, neg_h, neg_r, neg_t, out);
}

// round 13
// speedup vs baseline: 1.0695x; 1.0117x over previous
#include <cuda_runtime.h>

// SparseTransE on GB300 — R13.
// R3 structure (best measured: 40.0 µs; 1 triple/warp, two-phase reduction,
// 32 regs, 256-thread blocks) + L2::256B fetch-granularity hint on the six
// row loads. Rows are 1024 contiguous bytes and fully consumed, so 256B
// fetch granularity halves DRAM request count per row with zero over-fetch.
// R12's algebraic single-phase variant measured slower (41.4) — reverted.
//
// Inputs (metadata order):
//   d_in[0] all_emb  : float32 [501000, 256]
//   d_in[1..3] pos_h/r/t : int32 [65536]
//   d_in[4..6] neg_h/r/t : int32 [65536]
// Output: float32 [131072] = concat(pos_scores, neg_scores)
//
// score(h,r,t) = -|| e[h]/max(||e[h]||,eps) + e[r+n_ent] - e[t]/max(||e[t]||,eps) ||^2

#define N_BATCH 65536
#define EMB     256
#define N_ENT   500000
#define EPS2    1e-24f   // (1e-12)^2 — guard matches max(norm, 1e-12)

// Read-only vector load with 256B L2 fetch granularity.
__device__ __forceinline__ float4 ldg256(const float4* p) {
    float4 v;
    asm("ld.global.nc.L2::256B.v4.f32 {%0,%1,%2,%3}, [%4];"
        : "=f"(v.x), "=f"(v.y), "=f"(v.z), "=f"(v.w)
        : "l"(p));
    return v;
}

__global__ __launch_bounds__(256)
void sparse_transe_kernel(
    const float* __restrict__ emb,
    const int*   __restrict__ pos_h,
    const int*   __restrict__ pos_r,
    const int*   __restrict__ pos_t,
    const int*   __restrict__ neg_h,
    const int*   __restrict__ neg_r,
    const int*   __restrict__ neg_t,
    float*       __restrict__ out)
{
    const int gwarp = (blockIdx.x * blockDim.x + threadIdx.x) >> 5;  // 0..131071
    const int lane  = threadIdx.x & 31;

    const int* __restrict__ H;
    const int* __restrict__ R;
    const int* __restrict__ T;
    int i;
    if (gwarp < N_BATCH) { H = pos_h; R = pos_r; T = pos_t; i = gwarp; }
    else                 { H = neg_h; R = neg_r; T = neg_t; i = gwarp - N_BATCH; }

    // Warp-uniform index loads — broadcast.
    const long hrow = (long)__ldg(H + i) * EMB;
    const long trow = (long)__ldg(T + i) * EMB;
    const long rrow = ((long)__ldg(R + i) + N_ENT) * EMB;

    const float4* __restrict__ hp = (const float4*)(emb + hrow);
    const float4* __restrict__ tp = (const float4*)(emb + trow);
    const float4* __restrict__ rp = (const float4*)(emb + rrow);

    // Front-batch all 6 loads (entity rows first — DRAM latency; relation
    // rows are L2-resident). 256B fetch granularity: each 1KB row = 4 fetches.
    float4 h0 = ldg256(hp + lane);
    float4 h1 = ldg256(hp + lane + 32);
    float4 t0 = ldg256(tp + lane);
    float4 t1 = ldg256(tp + lane + 32);
    float4 r0 = ldg256(rp + lane);
    float4 r1 = ldg256(rp + lane + 32);

    // Partial squared norms of h and t.
    float sh = h0.x*h0.x + h0.y*h0.y + h0.z*h0.z + h0.w*h0.w
             + h1.x*h1.x + h1.y*h1.y + h1.z*h1.z + h1.w*h1.w;
    float st = t0.x*t0.x + t0.y*t0.y + t0.z*t0.z + t0.w*t0.w
             + t1.x*t1.x + t1.y*t1.y + t1.z*t1.z + t1.w*t1.w;

    // Fused butterfly reduction of (sh, st).
    #pragma unroll
    for (int off = 16; off > 0; off >>= 1) {
        sh += __shfl_xor_sync(0xffffffffu, sh, off);
        st += __shfl_xor_sync(0xffffffffu, st, off);
    }

    const float inv_h = rsqrtf(fmaxf(sh, EPS2));
    const float inv_t = rsqrtf(fmaxf(st, EPS2));

    // v = h/|h| + r - t/|t| ; accumulate v^2
    float acc = 0.f;
    {
        float d;
        d = fmaf(h0.x, inv_h, r0.x) - t0.x * inv_t; acc = fmaf(d, d, acc);
        d = fmaf(h0.y, inv_h, r0.y) - t0.y * inv_t; acc = fmaf(d, d, acc);
        d = fmaf(h0.z, inv_h, r0.z) - t0.z * inv_t; acc = fmaf(d, d, acc);
        d = fmaf(h0.w, inv_h, r0.w) - t0.w * inv_t; acc = fmaf(d, d, acc);
        d = fmaf(h1.x, inv_h, r1.x) - t1.x * inv_t; acc = fmaf(d, d, acc);
        d = fmaf(h1.y, inv_h, r1.y) - t1.y * inv_t; acc = fmaf(d, d, acc);
        d = fmaf(h1.z, inv_h, r1.z) - t1.z * inv_t; acc = fmaf(d, d, acc);
        d = fmaf(h1.w, inv_h, r1.w) - t1.w * inv_t; acc = fmaf(d, d, acc);
    }

    #pragma unroll
    for (int off = 16; off > 0; off >>= 1)
        acc += __shfl_xor_sync(0xffffffffu, acc, off);

    if (lane == 0)
        out[gwarp] = -acc;
}

extern "C" void kernel_launch(void* const* d_in, const int* in_sizes, int n_in,
                              void* d_out, int out_size)
{
    const float* emb   = (const float*)d_in[0];
    const int*   pos_h = (const int*)d_in[1];
    const int*   pos_r = (const int*)d_in[2];
    const int*   pos_t = (const int*)d_in[3];
    const int*   neg_h = (const int*)d_in[4];
    const int*   neg_r = (const int*)d_in[5];
    const int*   neg_t = (const int*)d_in[6];
    float* out = (float*)d_out;

    // 131072 warps, 8 warps (256 threads) per block -> 16384 blocks.
    const int blocks = (2 * N_BATCH) / 8;
    sparse_transe_kernel<<<blocks, 256>>>(
        emb, pos_h, pos_r, pos_t, neg_h, neg_r, neg_t, out);
}